// round 2
// baseline (speedup 1.0000x reference)
#include <cuda_runtime.h>
#include <stdint.h>

#define N 2048
#define MAXC 128            // padded per-column CSC capacity (col nnz ~17 mean)

// ---- device scratch (statically zero-initialized; no runtime allocation) ----
__device__ int   g_row_nnz[N];
__device__ int   g_rowptr[N + 1];
__device__ int   g_col_cnt[N];          // reset to 0 by k_cols each run
__device__ int   g_csc[N * MAXC];       // packed (t << 16) | u
__device__ float g_xT[4 * N * 32];      // xT[i*32 + b], i in [0, 8192)
__device__ float g_outT[4 * N * 32];    // outT[j*32 + b], j in [0, 8192)
__device__ unsigned int g_done;         // last-block flag; reset each run

// ============================================================================
// Kernel A (grid=2048, block=256):
//   - every block u: scan adjacency row u, rank nonzeros, scatter (t,u) to CSC
//   - blocks 0..255 additionally transpose one 32x32 tile of inputs -> xT
//   - last block to finish: exclusive prefix scan row_nnz -> rowptr
// ============================================================================
__global__ void k_build(const float* __restrict__ A,
                        const float* __restrict__ inputs) {
    __shared__ float sh[32][33];
    __shared__ int warp_sums[8];
    __shared__ bool s_last;

    int tid = threadIdx.x;
    int u = blockIdx.x;
    int lane = tid & 31, wid = tid >> 5;

    // ---- transpose slice (blocks 0..255): inputs(32 x 8192) -> xT(8192 x 32)
    if (blockIdx.x < 256) {
        int i0 = blockIdx.x * 32;
#pragma unroll
        for (int k = 0; k < 4; k++) {
            int r = wid + 8 * k;            // 0..31
            sh[r][lane] = inputs[r * 8192 + i0 + lane];   // coalesced read
        }
        __syncthreads();
#pragma unroll
        for (int k = 0; k < 4; k++) {
            int r = wid + 8 * k;
            g_xT[(i0 + r) * 32 + lane] = sh[lane][r];     // coalesced write
        }
    }

    // ---- row scan: 256 threads x 8 elements (2 x float4)
    const float4* row = (const float4*)(A + (size_t)u * N);
    int myv[8];
    int cnt = 0;
#pragma unroll
    for (int q = 0; q < 2; q++) {
        float4 f = row[tid * 2 + q];
        int basev = (tid * 2 + q) * 4;
        if (f.x != 0.0f) myv[cnt++] = basev + 0;
        if (f.y != 0.0f) myv[cnt++] = basev + 1;
        if (f.z != 0.0f) myv[cnt++] = basev + 2;
        if (f.w != 0.0f) myv[cnt++] = basev + 3;
    }

    // block exclusive scan of cnt
    int inc = cnt;
#pragma unroll
    for (int off = 1; off < 32; off <<= 1) {
        int y = __shfl_up_sync(0xffffffffu, inc, off);
        if (lane >= off) inc += y;
    }
    if (lane == 31) warp_sums[wid] = inc;
    __syncthreads();
    if (wid == 0) {
        int w = (lane < 8) ? warp_sums[lane] : 0;
#pragma unroll
        for (int off = 1; off < 8; off <<= 1) {
            int y = __shfl_up_sync(0xffffffffu, w, off);
            if (lane >= off) w += y;
        }
        if (lane < 8) warp_sums[lane] = w;
    }
    __syncthreads();
    int excl = inc - cnt + ((wid > 0) ? warp_sums[wid - 1] : 0);

    for (int e = 0; e < cnt; e++) {
        int v = myv[e];
        int t = excl + e;
        int slot = atomicAdd(&g_col_cnt[v], 1);
        if (slot < MAXC) g_csc[v * MAXC + slot] = (t << 16) | u;
    }
    if (tid == 0) g_row_nnz[u] = warp_sums[7];

    // ---- last-block prefix scan of row_nnz -> rowptr
    __threadfence();
    if (tid == 0) {
        unsigned r = atomicAdd(&g_done, 1u);
        s_last = (r == gridDim.x - 1);
    }
    __syncthreads();
    if (!s_last) return;

    // 256 threads x 8 contiguous values
    int loc[8];
    int s = 0;
    int base8 = tid * 8;
#pragma unroll
    for (int k = 0; k < 8; k++) { loc[k] = g_row_nnz[base8 + k]; s += loc[k]; }
    int inc2 = s;
#pragma unroll
    for (int off = 1; off < 32; off <<= 1) {
        int y = __shfl_up_sync(0xffffffffu, inc2, off);
        if (lane >= off) inc2 += y;
    }
    if (lane == 31) warp_sums[wid] = inc2;
    __syncthreads();
    if (wid == 0) {
        int w = (lane < 8) ? warp_sums[lane] : 0;
#pragma unroll
        for (int off = 1; off < 8; off <<= 1) {
            int y = __shfl_up_sync(0xffffffffu, w, off);
            if (lane >= off) w += y;
        }
        if (lane < 8) warp_sums[lane] = w;
    }
    __syncthreads();
    int run = inc2 - s + ((wid > 0) ? warp_sums[wid - 1] : 0);
#pragma unroll
    for (int k = 0; k < 8; k++) { g_rowptr[base8 + k] = run; run += loc[k]; }
    if (tid == 255) g_rowptr[N] = run;
    if (tid == 0) g_done = 0;          // reset for next graph replay
}

// ============================================================================
// Kernel B (grid=2048, block=128): one block per output column v.
//   Phase 1: load + deterministic rank-sort of incoming edges (by u).
//   Phase 2: cooperative high-MLP prefetch of all 16*cnt weights into SMEM.
//   Phase 3: compute 128 (c,b) outputs with 4 independent accumulators.
// ============================================================================
__global__ void k_cols(const float* __restrict__ ker,
                       const float* __restrict__ bias,
                       int nnz4) {
    int v = blockIdx.x;
    int tid = threadIdx.x;
    int c = tid >> 5, b = tid & 31;

    __shared__ int s_cnt;
    __shared__ int tmp_u[MAXC], tmp_t[MAXC];
    __shared__ int s_u[MAXC], s_base[MAXC], s_rn[MAXC];
    __shared__ float s_w[MAXC * 16];

    if (tid == 0) {
        int cc = g_col_cnt[v];
        s_cnt = (cc > MAXC) ? MAXC : cc;
        g_col_cnt[v] = 0;               // reset for next graph replay
    }
    __syncthreads();
    int cnt = s_cnt;

    if (tid < cnt) {
        int p = g_csc[v * MAXC + tid];
        tmp_u[tid] = p & 0xffff;
        tmp_t[tid] = p >> 16;
    }
    __syncthreads();
    if (tid < cnt) {
        int myu = tmp_u[tid];
        int r = 0;
        for (int e = 0; e < cnt; e++) r += (tmp_u[e] < myu);
        s_u[r] = myu;
        s_base[r] = 4 * g_rowptr[myu] + tmp_t[tid];
        s_rn[r] = g_row_nnz[myu];
    }
    __syncthreads();

    // cooperative weight prefetch: all cnt*16 scattered loads in parallel
    int total = cnt * 16;
    for (int idx = tid; idx < total; idx += 128) {
        int e = idx >> 4, w = idx & 15;
        int ic = w >> 2, cc = w & 3;
        s_w[idx] = __ldg(&ker[ic * nnz4 + s_base[e] + cc * s_rn[e]]);
    }
    __syncthreads();

    float a0 = 0.f, a1 = 0.f, a2 = 0.f, a3 = 0.f;
    const float* xb = g_xT + b;
#pragma unroll 4
    for (int e = 0; e < cnt; e++) {
        int u = s_u[e];
        const float* xr = xb + u * 32;
        const float* we = s_w + e * 16 + c;
        a0 += xr[0]      * we[0];
        a1 += xr[65536]  * we[4];
        a2 += xr[131072] * we[8];
        a3 += xr[196608] * we[12];
    }
    int j = c * N + v;
    g_outT[(size_t)j * 32 + b] = (a0 + a1) + (a2 + a3) + __ldg(&bias[j]);
}

// ============================================================================
// Kernel C: transpose outT (8192 x 32) -> out (32 x 8192), fully coalesced.
// ============================================================================
__global__ void k_outT(float* __restrict__ out) {
    __shared__ float sh[32][33];
    int j0 = blockIdx.x * 32;
    int tx = threadIdx.x, ty = threadIdx.y;
    sh[ty][tx] = g_outT[(j0 + ty) * 32 + tx];
    __syncthreads();
    out[ty * 8192 + j0 + tx] = sh[tx][ty];
}

extern "C" void kernel_launch(void* const* d_in, const int* in_sizes, int n_in,
                              void* d_out, int out_size) {
    const float* inputs = (const float*)d_in[0];  // (32, 8192)
    const float* A      = (const float*)d_in[1];  // (2048, 2048)
    const float* ker    = (const float*)d_in[2];  // (16*NNZ,)
    const float* bias   = (const float*)d_in[3];  // (8192,)
    float* out = (float*)d_out;

    int nnz4 = in_sizes[2] / 4;   // = 4*NNZ

    k_build<<<N, 256>>>(A, inputs);
    k_cols<<<N, 128>>>(ker, bias, nnz4);
    dim3 t32x32(32, 32);
    k_outT<<<256, t32x32>>>(out);
}